// round 13
// baseline (speedup 1.0000x reference)
#include <cuda_runtime.h>
#include <cstddef>

// KitNET_5257039970983 — R11: R7 verbatim (constant-bank folded weights,
// warp-local staging, unroll-1 tile loop, dual-accumulator compute) with
// tails moved to shared memory to cut registers 80 -> <=64, enabling
// 4 blocks/SM (32 warps). __launch_bounds__(256,4).
// Output: head_out(B,10) then tails(B,10), fp32.

#define NTILES 10
#define CDIM   10
#define HDIM   7
#define FDIM   100
#define TPB    256
#define RPB    512
#define PSTR   11                 // u64 per pair-row (88B, conflict-free LDS/STS)
#define SLICE_U64 (32*PSTR)       // 352 u64 = 2816 B per warp
#define TSTR   11                 // u64 stride for tails rows (2-way conflict max)

typedef unsigned long long u64;

struct FoldData {
    ulonglong2 MT[500];   // [t][co][ci pair]  (m,m)-packed
    ulonglong2 BT[50];    // [t][co pair]
    ulonglong2 MH[50];    // [j][i pair]
    ulonglong2 BH[5];
    int perm[100];
    int tbase[10];
    int pad[2];
};

__device__   FoldData gF;
__constant__ FoldData cF;

__device__ __forceinline__ u64 fma2(u64 a, u64 b, u64 c) {
    u64 d;
    asm("fma.rn.f32x2 %0, %1, %2, %3;" : "=l"(d) : "l"(a), "l"(b), "l"(c));
    return d;
}
__device__ __forceinline__ u64 pack2(float x, float y) {
    u64 d;
    asm("mov.b64 %0, {%1, %2};" : "=l"(d) : "f"(x), "f"(y));
    return d;
}
__device__ __forceinline__ void unpack2(u64 a, float& x, float& y) {
    asm("mov.b64 {%0, %1}, %2;" : "=f"(x), "=f"(y) : "l"(a));
}

// ================= setup kernel: fold weights into gF (1 block) =================
__global__ void kitnet_setup(const float* __restrict__ Wt,
                             const float* __restrict__ hbt,
                             const float* __restrict__ vbt,
                             const float* __restrict__ Wh,
                             const float* __restrict__ hbh,
                             const float* __restrict__ vbh,
                             const int*   __restrict__ clusters)
{
    __shared__ float sW[700], sHB[70], sVB[100], sWH[70], sHBH[7], sVBH[10];
    const int tid = threadIdx.x;
    for (int i = tid; i < 700; i += TPB) sW[i]  = Wt[i];
    for (int i = tid; i < 70;  i += TPB) sHB[i] = hbt[i];
    for (int i = tid; i < 100; i += TPB) sVB[i] = vbt[i];
    for (int i = tid; i < 70;  i += TPB) sWH[i] = Wh[i];
    if (tid < HDIM)   sHBH[tid] = hbh[tid];
    if (tid < NTILES) sVBH[tid] = vbh[tid];
    __syncthreads();

    float2* MT2 = (float2*)gF.MT;
    float2* BT2 = (float2*)gF.BT;
    float2* MH2 = (float2*)gF.MH;
    float2* BH2 = (float2*)gF.BH;

    for (int i = tid; i < NTILES * CDIM * CDIM; i += TPB) {
        int t  = i / 100;
        int r  = i - t * 100;
        int co = r / 10;
        int ci = r - co * 10;
        float m = (ci == co) ? -1.0f : 0.0f;
        #pragma unroll
        for (int h = 0; h < HDIM; ++h)
            m += sW[t * 70 + h * 10 + ci] * sW[t * 70 + h * 10 + co];
        MT2[i] = make_float2(m, m);
    }
    for (int i = tid; i < NTILES * CDIM; i += TPB) {
        int t = i / 10, c = i - t * 10;
        float b = sVB[i];
        #pragma unroll
        for (int h = 0; h < HDIM; ++h)
            b += sHB[t * HDIM + h] * sW[t * 70 + h * 10 + c];
        BT2[i] = make_float2(b, b);
    }
    for (int i = tid; i < CDIM * CDIM; i += TPB) {
        int j = i / 10, ii = i - j * 10;
        float m = 0.0f;
        #pragma unroll
        for (int h = 0; h < HDIM; ++h)
            m += sWH[h * 10 + ii] * sWH[h * 10 + j];
        MH2[i] = make_float2(m, m);
    }
    if (tid < NTILES) {
        float b = sVBH[tid];
        #pragma unroll
        for (int h = 0; h < HDIM; ++h)
            b += sHBH[h] * sWH[h * 10 + tid];
        BH2[tid] = make_float2(b, b);
    }
    for (int i = tid; i < FDIM; i += TPB) gF.perm[i] = clusters[i];
    if (tid < NTILES) {
        const int* pp = clusters + tid * 10;
        int b0 = pp[0];
        bool ok = ((b0 & 1) == 0);
        #pragma unroll
        for (int j = 1; j < 10; ++j) ok = ok && (pp[j] == b0 + j);
        gF.tbase[tid] = ok ? b0 : -1;
    }
}

// ================= main kernel =================

// warp-local staging: one tile's 10 cols for this warp's 32 pairs -> regs
__device__ __forceinline__ void stage_load(const float* __restrict__ x, float rv[20],
                                           int t, int rowbase, int B, int lane)
{
    const int tb = cF.tbase[t];
    if (tb >= 0) {
        #pragma unroll
        for (int i = 0; i < 10; ++i) {
            int id = 32*i + lane;                  // 0..319
            int p  = id / 10;
            int rem = id - 10*p;
            int h  = rem / 5;
            int k  = rem - 5*h;
            int row = rowbase + p + h*256;
            float2 v = make_float2(0.0f, 0.0f);
            if (row < B) v = *(const float2*)(x + (size_t)row*FDIM + tb + 2*k);
            rv[2*i]   = v.x;
            rv[2*i+1] = v.y;
        }
    } else {
        const int* pp = cF.perm + t * 10;
        #pragma unroll
        for (int i = 0; i < 20; ++i) {
            int id = 32*i + lane;                  // 0..639
            int p  = id / 20;
            int rem = id - 20*p;
            int h  = rem / 10;
            int j  = rem - 10*h;
            int row = rowbase + p + h*256;
            float v = 0.0f;
            if (row < B) v = x[(size_t)row*FDIM + pp[j]];
            rv[i] = v;
        }
    }
}

__device__ __forceinline__ void stage_store(float* __restrict__ slf, const float rv[20],
                                            int t, int lane)
{
    const int tb = cF.tbase[t];
    if (tb >= 0) {
        #pragma unroll
        for (int i = 0; i < 10; ++i) {
            int id = 32*i + lane;
            int p  = id / 10;
            int rem = id - 10*p;
            int h  = rem / 5;
            int k  = rem - 5*h;
            slf[p*22 + 4*k + h]     = rv[2*i];
            slf[p*22 + 4*k + 2 + h] = rv[2*i+1];
        }
    } else {
        #pragma unroll
        for (int i = 0; i < 20; ++i) {
            int id = 32*i + lane;
            int p  = id / 20;
            int rem = id - 20*p;
            int h  = rem / 10;
            int j  = rem - 10*h;
            slf[p*22 + 2*j + h] = rv[i];
        }
    }
}

// err = xc @ M_t + b_t with M/b from constant bank ; packed sum of squares
__device__ __forceinline__ u64 compute_tile(const u64 xc[CDIM], int t)
{
    const int mb = t * 50;
    const int bb0 = t * 5;
    u64 sq = 0ull;
    #pragma unroll
    for (int cp = 0; cp < 5; ++cp) {
        ulonglong2 bb = cF.BT[bb0 + cp];
        u64 a0 = bb.x, a1 = bb.y;
        #pragma unroll
        for (int cc = 0; cc < 5; ++cc) {
            ulonglong2 w0 = cF.MT[mb + (2*cp)   * 5 + cc];
            ulonglong2 w1 = cF.MT[mb + (2*cp+1) * 5 + cc];
            a0 = fma2(xc[2*cc],   w0.x, a0);
            a0 = fma2(xc[2*cc+1], w0.y, a0);
            a1 = fma2(xc[2*cc],   w1.x, a1);
            a1 = fma2(xc[2*cc+1], w1.y, a1);
        }
        sq = fma2(a0, a0, sq);
        sq = fma2(a1, a1, sq);
    }
    return sq;
}

__global__ void __launch_bounds__(TPB, 4) kitnet_main(
    const float* __restrict__ x,
    float* __restrict__ out,
    int B)
{
    __shared__ u64 xs[8 * SLICE_U64];          // 22528 B (x slices)
    __shared__ u64 tls[8 * 32 * TSTR];         // 22528 B (tails, per warp 32x11)

    const int tid  = threadIdx.x;
    const int lane = tid & 31;
    const int wid  = tid >> 5;
    const int base = blockIdx.x * RPB;

    const int rowbase = base + wid * 32;
    u64*   xsw = xs + wid * SLICE_U64;
    float* slf = (float*)xsw;
    u64*   tlw = tls + wid * 32 * TSTR + lane * TSTR;

    float rv[20];

    // stage tile 0
    stage_load(x, rv, 0, rowbase, B, lane);
    stage_store(slf, rv, 0, lane);
    __syncwarp();

    #pragma unroll 1
    for (int t = 0; t < NTILES; ++t) {
        if (t < NTILES - 1)
            stage_load(x, rv, t + 1, rowbase, B, lane);

        u64 xc[CDIM];
        #pragma unroll
        for (int j = 0; j < CDIM; ++j) xc[j] = xsw[lane * PSTR + j];

        u64 sq = compute_tile(xc, t);
        float e0, e1;
        unpack2(sq, e0, e1);
        // 0.5*log(0.1*e) = 0.5*log(e) - 0.5*log(10)
        tlw[t] = pack2(__fmaf_rn(0.5f, __logf(e0), -1.15129255f),
                       __fmaf_rn(0.5f, __logf(e1), -1.15129255f));

        __syncwarp();                          // all lanes done reading slice
        if (t < NTILES - 1)
            stage_store(slf, rv, t + 1, lane);
        __syncwarp();                          // writes visible for next xc load
    }

    // ---- reload tails (rv now dead -> register headroom) ----
    u64 tails[NTILES];
    #pragma unroll
    for (int n = 0; n < NTILES; ++n) tails[n] = tlw[n];

    // ---- head: head_out = tails @ MH^T + b_h (constant-bank weights) ----
    u64 ho[NTILES];
    #pragma unroll
    for (int jp = 0; jp < 5; ++jp) {
        ulonglong2 bb = cF.BH[jp];
        u64 a0 = bb.x, a1 = bb.y;
        #pragma unroll
        for (int tt = 0; tt < 5; ++tt) {
            ulonglong2 w0 = cF.MH[(2*jp)   * 5 + tt];
            ulonglong2 w1 = cF.MH[(2*jp+1) * 5 + tt];
            a0 = fma2(tails[2*tt],   w0.x, a0);
            a0 = fma2(tails[2*tt+1], w0.y, a0);
            a1 = fma2(tails[2*tt],   w1.x, a1);
            a1 = fma2(tails[2*tt+1], w1.y, a1);
        }
        ho[2*jp]   = a0;
        ho[2*jp+1] = a1;
    }

    // ---- warp-local output restage: round 0 = head, round 1 = tails ----
    const long long B10 = (long long)B * NTILES;
    #pragma unroll 1
    for (int r = 0; r < 2; ++r) {
        const u64* src = r ? tails : ho;
        #pragma unroll
        for (int n = 0; n < NTILES; ++n) {
            float a, b;
            unpack2(src[n], a, b);
            slf[lane * 10 + n]       = a;      // rows rowbase..+32
            slf[320 + lane * 10 + n] = b;      // rows rowbase+256..+32
        }
        __syncwarp();
        const long long bound = (long long)(r + 1) * B10;
        #pragma unroll
        for (int i = 0; i < 5; ++i) {
            int q  = lane + 32 * i;            // 0..159 float4 index
            int h  = (q >= 80) ? 1 : 0;
            int qq = q - 80 * h;
            long long off = (long long)r * B10
                          + (long long)(rowbase + h * 256) * 10 + 4 * qq;
            float4 v = *(const float4*)(slf + h * 320 + 4 * qq);
            if (off + 4 <= bound) {
                *(float4*)(out + off) = v;
            } else {
                const float* vf = (const float*)&v;
                #pragma unroll
                for (int kk = 0; kk < 4; ++kk)
                    if (off + kk < bound) out[off + kk] = vf[kk];
            }
        }
        __syncwarp();
    }
}

extern "C" void kernel_launch(void* const* d_in, const int* in_sizes, int n_in,
                              void* d_out, int out_size)
{
    const float* x   = (const float*)d_in[0];
    const float* Wt  = (const float*)d_in[1];
    const float* hbt = (const float*)d_in[2];
    const float* vbt = (const float*)d_in[3];
    const float* Wh  = (const float*)d_in[4];
    const float* hbh = (const float*)d_in[5];
    const float* vbh = (const float*)d_in[6];
    const int*   cls = (const int*)d_in[7];

    const int B = in_sizes[0] / FDIM;
    const int grid = (B + RPB - 1) / RPB;

    kitnet_setup<<<1, TPB>>>(Wt, hbt, vbt, Wh, hbh, vbh, cls);

    void* gfp = nullptr;
    cudaGetSymbolAddress(&gfp, gF);
    cudaMemcpyToSymbolAsync(cF, gfp, sizeof(FoldData), 0,
                            cudaMemcpyDeviceToDevice, 0);

    kitnet_main<<<grid, TPB>>>(x, (float*)d_out, B);
}

// round 14
// speedup vs baseline: 1.3266x; 1.3266x over previous
#include <cuda_runtime.h>
#include <cstddef>

// KitNET_5257039970983 — R12: R7 verbatim (constant-bank folded weights,
// warp-local, unroll-1 loop, dual-accumulator compute, 80-reg/3-block point)
// with register staging replaced by cp.async (LDGSTS) into ping-pong slices:
// no LDG->STS scoreboard stall, no rv registers.
// Output: head_out(B,10) then tails(B,10), fp32.

#define NTILES 10
#define CDIM   10
#define HDIM   7
#define FDIM   100
#define TPB    256
#define RPB    512
#define PSTR   11                 // u64 per pair-row (88B, conflict-free LDS.64)
#define SLICE_U64 (32*PSTR)       // 352 u64 = 2816 B per warp per buffer

typedef unsigned long long u64;

struct FoldData {
    ulonglong2 MT[500];   // [t][co][ci pair]  (m,m)-packed
    ulonglong2 BT[50];    // [t][co pair]
    ulonglong2 MH[50];    // [j][i pair]
    ulonglong2 BH[5];
    int perm[100];
    int tbase[10];
    int pad[2];
};

__device__   FoldData gF;
__constant__ FoldData cF;

__device__ __forceinline__ u64 fma2(u64 a, u64 b, u64 c) {
    u64 d;
    asm("fma.rn.f32x2 %0, %1, %2, %3;" : "=l"(d) : "l"(a), "l"(b), "l"(c));
    return d;
}
__device__ __forceinline__ u64 pack2(float x, float y) {
    u64 d;
    asm("mov.b64 %0, {%1, %2};" : "=l"(d) : "f"(x), "f"(y));
    return d;
}
__device__ __forceinline__ void unpack2(u64 a, float& x, float& y) {
    asm("mov.b64 {%0, %1}, %2;" : "=f"(x), "=f"(y) : "l"(a));
}
__device__ __forceinline__ unsigned smem_u32(const void* p) {
    unsigned a;
    asm("{ .reg .u64 t; cvta.to.shared.u64 t, %1; cvt.u32.u64 %0, t; }"
        : "=r"(a) : "l"(p));
    return a;
}
__device__ __forceinline__ void cp4(unsigned dst, const float* src) {
    asm volatile("cp.async.ca.shared.global [%0], [%1], 4;"
                 :: "r"(dst), "l"(src));
}
#define CP_COMMIT() asm volatile("cp.async.commit_group;" ::: "memory")
#define CP_WAIT(n)  asm volatile("cp.async.wait_group %0;" :: "n"(n) : "memory")

// ================= setup kernel: fold weights into gF (1 block) =================
__global__ void kitnet_setup(const float* __restrict__ Wt,
                             const float* __restrict__ hbt,
                             const float* __restrict__ vbt,
                             const float* __restrict__ Wh,
                             const float* __restrict__ hbh,
                             const float* __restrict__ vbh,
                             const int*   __restrict__ clusters)
{
    __shared__ float sW[700], sHB[70], sVB[100], sWH[70], sHBH[7], sVBH[10];
    const int tid = threadIdx.x;
    for (int i = tid; i < 700; i += TPB) sW[i]  = Wt[i];
    for (int i = tid; i < 70;  i += TPB) sHB[i] = hbt[i];
    for (int i = tid; i < 100; i += TPB) sVB[i] = vbt[i];
    for (int i = tid; i < 70;  i += TPB) sWH[i] = Wh[i];
    if (tid < HDIM)   sHBH[tid] = hbh[tid];
    if (tid < NTILES) sVBH[tid] = vbh[tid];
    __syncthreads();

    float2* MT2 = (float2*)gF.MT;
    float2* BT2 = (float2*)gF.BT;
    float2* MH2 = (float2*)gF.MH;
    float2* BH2 = (float2*)gF.BH;

    for (int i = tid; i < NTILES * CDIM * CDIM; i += TPB) {
        int t  = i / 100;
        int r  = i - t * 100;
        int co = r / 10;
        int ci = r - co * 10;
        float m = (ci == co) ? -1.0f : 0.0f;
        #pragma unroll
        for (int h = 0; h < HDIM; ++h)
            m += sW[t * 70 + h * 10 + ci] * sW[t * 70 + h * 10 + co];
        MT2[i] = make_float2(m, m);
    }
    for (int i = tid; i < NTILES * CDIM; i += TPB) {
        int t = i / 10, c = i - t * 10;
        float b = sVB[i];
        #pragma unroll
        for (int h = 0; h < HDIM; ++h)
            b += sHB[t * HDIM + h] * sW[t * 70 + h * 10 + c];
        BT2[i] = make_float2(b, b);
    }
    for (int i = tid; i < CDIM * CDIM; i += TPB) {
        int j = i / 10, ii = i - j * 10;
        float m = 0.0f;
        #pragma unroll
        for (int h = 0; h < HDIM; ++h)
            m += sWH[h * 10 + ii] * sWH[h * 10 + j];
        MH2[i] = make_float2(m, m);
    }
    if (tid < NTILES) {
        float b = sVBH[tid];
        #pragma unroll
        for (int h = 0; h < HDIM; ++h)
            b += sHBH[h] * sWH[h * 10 + tid];
        BH2[tid] = make_float2(b, b);
    }
    for (int i = tid; i < FDIM; i += TPB) gF.perm[i] = clusters[i];
    if (tid < NTILES) {
        const int* pp = clusters + tid * 10;
        int b0 = pp[0];
        bool ok = true;                     // 4B copies: no parity constraint
        #pragma unroll
        for (int j = 1; j < 10; ++j) ok = ok && (pp[j] == b0 + j);
        gF.tbase[tid] = ok ? b0 : -1;
    }
}

// ================= main kernel =================

// err = xc @ M_t + b_t with M/b from constant bank ; packed sum of squares
__device__ __forceinline__ u64 compute_tile(const u64 xc[CDIM], int t)
{
    const int mb = t * 50;
    const int bb0 = t * 5;
    u64 sq = 0ull;
    #pragma unroll
    for (int cp = 0; cp < 5; ++cp) {
        ulonglong2 bb = cF.BT[bb0 + cp];
        u64 a0 = bb.x, a1 = bb.y;
        #pragma unroll
        for (int cc = 0; cc < 5; ++cc) {
            ulonglong2 w0 = cF.MT[mb + (2*cp)   * 5 + cc];
            ulonglong2 w1 = cF.MT[mb + (2*cp+1) * 5 + cc];
            a0 = fma2(xc[2*cc],   w0.x, a0);
            a0 = fma2(xc[2*cc+1], w0.y, a0);
            a1 = fma2(xc[2*cc],   w1.x, a1);
            a1 = fma2(xc[2*cc+1], w1.y, a1);
        }
        sq = fma2(a0, a0, sq);
        sq = fma2(a1, a1, sq);
    }
    return sq;
}

__global__ void __launch_bounds__(TPB, 3) kitnet_main(
    const float* __restrict__ x,
    float* __restrict__ out,
    int B)
{
    __shared__ u64 xs[2][8 * SLICE_U64];       // 2 x 22528 B ping-pong

    const int tid  = threadIdx.x;
    const int lane = tid & 31;
    const int wid  = tid >> 5;
    const int base = blockIdx.x * RPB;
    const int rowbase = base + wid * 32;
    const float* xg = x + (size_t)rowbase * FDIM;

    u64* bufA = xs[0] + wid * SLICE_U64;
    u64* bufB = xs[1] + wid * SLICE_U64;
    const unsigned dbA = smem_u32(bufA);
    const unsigned dbB = smem_u32(bufB);

    // per-lane map: item i -> (p,h,j); emap = srcoff(17b) | dstoff<<17
    // srcoff = clamped_rowoff*100 + j ; dstoff = p*22 + 2j + h (floats)
    int emap[20];
    #pragma unroll
    for (int i = 0; i < 20; ++i) {
        int id  = 32*i + lane;                 // 0..639
        int p   = id / 20;
        int rem = id - 20*p;
        int h   = rem / 10;
        int j   = rem - 10*h;
        int row = rowbase + p + h*256;
        int roff = (row < B ? row : (B - 1)) - rowbase;   // clamp (dup reads ok)
        emap[i] = (roff * FDIM + j) | ((p*22 + 2*j + h) << 17);
    }

    // issue one tile's 640 4B copies (20 per lane)
    auto stage_issue = [&](unsigned db, int t) {
        const int tb = cF.tbase[t];
        if (tb >= 0) {
            #pragma unroll
            for (int i = 0; i < 20; ++i) {
                int e = emap[i];
                cp4(db + (unsigned)(e >> 17) * 4u, xg + (e & 0x1FFFF) + tb);
            }
        } else {
            const int* pp = cF.perm + t * 10;
            #pragma unroll
            for (int i = 0; i < 20; ++i) {
                int id  = 32*i + lane;
                int p   = id / 20;
                int rem = id - 20*p;
                int h   = rem / 10;
                int j   = rem - 10*h;
                int e   = emap[i];
                int rbase = (e & 0x1FFFF) - j;            // clamped rowoff*100
                cp4(db + (unsigned)(e >> 17) * 4u, xg + rbase + pp[j]);
            }
        }
        CP_COMMIT();
    };

    u64 tails[NTILES];

    stage_issue(dbA, 0);

    #pragma unroll 1
    for (int t = 0; t < NTILES; ++t) {
        if (t < NTILES - 1) {
            stage_issue((t & 1) ? dbA : dbB, t + 1);
            CP_WAIT(1);                        // tile t's group complete
        } else {
            CP_WAIT(0);
        }
        __syncwarp();                          // all lanes' copies visible

        const u64* xsw = ((t & 1) ? bufB : bufA) + lane * PSTR;
        u64 xc[CDIM];
        #pragma unroll
        for (int j = 0; j < CDIM; ++j) xc[j] = xsw[j];

        u64 sq = compute_tile(xc, t);
        float e0, e1;
        unpack2(sq, e0, e1);
        // 0.5*log(0.1*e) = 0.5*log(e) - 0.5*log(10)
        tails[t] = pack2(__fmaf_rn(0.5f, __logf(e0), -1.15129255f),
                         __fmaf_rn(0.5f, __logf(e1), -1.15129255f));

        __syncwarp();                          // WAR: readers done before next issue
    }

    // ---- head: head_out = tails @ MH^T + b_h (constant-bank weights) ----
    u64 ho[NTILES];
    #pragma unroll
    for (int jp = 0; jp < 5; ++jp) {
        ulonglong2 bb = cF.BH[jp];
        u64 a0 = bb.x, a1 = bb.y;
        #pragma unroll
        for (int tt = 0; tt < 5; ++tt) {
            ulonglong2 w0 = cF.MH[(2*jp)   * 5 + tt];
            ulonglong2 w1 = cF.MH[(2*jp+1) * 5 + tt];
            a0 = fma2(tails[2*tt],   w0.x, a0);
            a0 = fma2(tails[2*tt+1], w0.y, a0);
            a1 = fma2(tails[2*tt],   w1.x, a1);
            a1 = fma2(tails[2*tt+1], w1.y, a1);
        }
        ho[2*jp]   = a0;
        ho[2*jp+1] = a1;
    }

    // ---- warp-local output restage (buffer A): round 0 = head, 1 = tails ----
    float* slf = (float*)bufA;
    const long long B10 = (long long)B * NTILES;
    #pragma unroll 1
    for (int r = 0; r < 2; ++r) {
        const u64* src = r ? tails : ho;
        #pragma unroll
        for (int n = 0; n < NTILES; ++n) {
            float a, b;
            unpack2(src[n], a, b);
            slf[lane * 10 + n]       = a;      // rows rowbase..+32
            slf[320 + lane * 10 + n] = b;      // rows rowbase+256..+32
        }
        __syncwarp();
        const long long bound = (long long)(r + 1) * B10;
        #pragma unroll
        for (int i = 0; i < 5; ++i) {
            int q  = lane + 32 * i;            // 0..159 float4 index
            int h  = (q >= 80) ? 1 : 0;
            int qq = q - 80 * h;
            long long off = (long long)r * B10
                          + (long long)(rowbase + h * 256) * 10 + 4 * qq;
            float4 v = *(const float4*)(slf + h * 320 + 4 * qq);
            if (off + 4 <= bound) {
                *(float4*)(out + off) = v;
            } else {
                const float* vf = (const float*)&v;
                #pragma unroll
                for (int kk = 0; kk < 4; ++kk)
                    if (off + kk < bound) out[off + kk] = vf[kk];
            }
        }
        __syncwarp();
    }
}

extern "C" void kernel_launch(void* const* d_in, const int* in_sizes, int n_in,
                              void* d_out, int out_size)
{
    const float* x   = (const float*)d_in[0];
    const float* Wt  = (const float*)d_in[1];
    const float* hbt = (const float*)d_in[2];
    const float* vbt = (const float*)d_in[3];
    const float* Wh  = (const float*)d_in[4];
    const float* hbh = (const float*)d_in[5];
    const float* vbh = (const float*)d_in[6];
    const int*   cls = (const int*)d_in[7];

    const int B = in_sizes[0] / FDIM;
    const int grid = (B + RPB - 1) / RPB;

    kitnet_setup<<<1, TPB>>>(Wt, hbt, vbt, Wh, hbh, vbh, cls);

    void* gfp = nullptr;
    cudaGetSymbolAddress(&gfp, gF);
    cudaMemcpyToSymbolAsync(cF, gfp, sizeof(FoldData), 0,
                            cudaMemcpyDeviceToDevice, 0);

    kitnet_main<<<grid, TPB>>>(x, (float*)d_out, B);
}